// round 9
// baseline (speedup 1.0000x reference)
#include <cuda_runtime.h>
#include <cstdint>

#define CC    512
#define TT    16
#define PP    576
#define NN    9216
#define CN    4718592
#define NHEAD 8
#define TOTAL 9437184

#define STR   36                   // GEMM: padded floats per SMEM row
#define SSZ   (2*128*STR)          // GEMM: floats per stage

// attention smem layout (floats) — 32-key tiles, double-buffered
#define KSTR  68
#define VSTR  72
#define OFF_V   (2*32*KSTR)              // 4352
#define OFF_PS  (OFF_V + 2*32*VSTR)      // 8960
#define OFF_AL  (OFF_PS + 64*KSTR)       // 13312
#define ATT_FLOATS (OFF_AL + 64)         // 13376
#define ATT_SMEM (ATT_FLOATS*4)          // 53504 B -> 4 blocks/SM

__device__ float g_xt[TOTAL];      // [tok][c]  (x + pos, tf32-rounded)
__device__ float g_q[TOTAL];       // token-major [b][t][p][512]
__device__ float g_k[TOTAL];
__device__ float g_v[TOTAL];
__device__ float g_attn[TOTAL];    // [tok][c]  (tf32-rounded)
__device__ float g_wr[4*CC*CC];    // tf32-rounded wq,wk,wv,wo

__device__ __forceinline__ float to_tf32(float x){
    float r; asm("cvt.rna.tf32.f32 %0, %1;" : "=f"(r) : "f"(x)); return r;
}
__device__ __forceinline__ uint32_t smem_u32(const void* p){
    uint32_t a;
    asm("{ .reg .u64 t; cvta.to.shared.u64 t, %1; cvt.u32.u64 %0, t; }"
        : "=r"(a) : "l"(p));
    return a;
}

__device__ __forceinline__ void mma8(float4& d,
    uint32_t a0, uint32_t a1, uint32_t a2, uint32_t a3,
    uint32_t b0, uint32_t b1)
{
    asm volatile(
        "mma.sync.aligned.m16n8k8.row.col.f32.tf32.tf32.f32 "
        "{%0,%1,%2,%3}, {%4,%5,%6,%7}, {%8,%9}, {%0,%1,%2,%3};"
        : "+f"(d.x), "+f"(d.y), "+f"(d.z), "+f"(d.w)
        : "r"(a0), "r"(a1), "r"(a2), "r"(a3), "r"(b0), "r"(b1));
}

// ---------------------------------------------------------------------------
// prep: round weights to tf32 into g_wr
// ---------------------------------------------------------------------------
__global__ void prep_w(const float* __restrict__ wq, const float* __restrict__ wk,
                       const float* __restrict__ wv, const float* __restrict__ wo){
    int i = blockIdx.x * 256 + threadIdx.x;
    g_wr[i]          = to_tf32(wq[i]);
    g_wr[262144 + i] = to_tf32(wk[i]);
    g_wr[524288 + i] = to_tf32(wv[i]);
    g_wr[786432 + i] = to_tf32(wo[i]);
}

// ---------------------------------------------------------------------------
// transpose x[b][c][n] + pos[c][t] -> g_xt[b*9216+n][c]  (tf32-rounded)
// ---------------------------------------------------------------------------
__global__ __launch_bounds__(256) void transpose_pos(
    const float* __restrict__ x, const float* __restrict__ pos){
    __shared__ float tile[32][33];
    const int n0 = blockIdx.x * 32, c0 = blockIdx.y * 32, b = blockIdx.z;
    const int tx = threadIdx.x & 31, ty = threadIdx.x >> 5;
    const int t = n0 / PP;
#pragma unroll
    for (int i = 0; i < 4; ++i){
        const int c = c0 + ty + i * 8;
        tile[ty + i * 8][tx] =
            to_tf32(x[((size_t)b * CC + c) * NN + n0 + tx] + pos[c * TT + t]);
    }
    __syncthreads();
#pragma unroll
    for (int i = 0; i < 4; ++i){
        const int n = n0 + ty + i * 8;
        g_xt[((size_t)b * NN + n) * CC + c0 + tx] = tile[tx][ty + i * 8];
    }
}

// ---------------------------------------------------------------------------
// mma.sync tf32 GEMM (validated in round 4)
// ---------------------------------------------------------------------------
template<int MODE>
__global__ __launch_bounds__(256) void gemm_mma(
    const float* __restrict__ bi0, const float* __restrict__ bi1,
    const float* __restrict__ bi2, float* __restrict__ o_out)
{
    extern __shared__ float sm[];

    const int tid = threadIdx.x;
    const int m0 = blockIdx.x * 128;
    const int n0 = blockIdx.y * 128;

    const float* A;
    const float* Bw;
    const float* bias;
    float* OUT;
    if (MODE == 0){
        const int pr = blockIdx.z;
        A    = g_xt + (size_t)m0 * CC;
        Bw   = g_wr + (size_t)pr * 262144 + (size_t)n0 * CC;
        bias = (pr == 0) ? bi0 : (pr == 1) ? bi1 : bi2;
        OUT  = (pr == 0) ? g_q : (pr == 1) ? g_k : g_v;
    } else {
        A    = g_attn + (size_t)m0 * CC;
        Bw   = g_wr + 786432 + (size_t)n0 * CC;
        bias = bi0;
        OUT  = o_out;
    }

    const int row_l = tid >> 3;
    const int jl    = tid & 7;
    const int wid = tid >> 5, lane = tid & 31;
    const int wm = wid >> 2, wn = wid & 3;
    const int r = lane >> 2, c = lane & 3;

    float4 pa[4], pb[4];

    auto ldg_tile = [&](int kt){
#pragma unroll
        for (int p = 0; p < 4; ++p){
            pa[p] = *(const float4*)(A  + (size_t)(row_l + p * 32) * CC + kt * 32 + jl * 4);
            pb[p] = *(const float4*)(Bw + (size_t)(row_l + p * 32) * CC + kt * 32 + jl * 4);
        }
    };
    auto sts_tile = [&](int buf){
        float* As = sm + buf * SSZ;
        float* Bs = As + 128 * STR;
#pragma unroll
        for (int p = 0; p < 4; ++p){
            const int ro = (row_l + p * 32) * STR;
            As[ro + 0 * 8 + jl] = pa[p].x;
            As[ro + 1 * 8 + jl] = pa[p].y;
            As[ro + 2 * 8 + jl] = pa[p].z;
            As[ro + 3 * 8 + jl] = pa[p].w;
            Bs[ro + 0 * 8 + jl] = pb[p].x;
            Bs[ro + 1 * 8 + jl] = pb[p].y;
            Bs[ro + 2 * 8 + jl] = pb[p].z;
            Bs[ro + 3 * 8 + jl] = pb[p].w;
        }
    };

    float4 acc[4][4];
#pragma unroll
    for (int i = 0; i < 4; ++i)
#pragma unroll
        for (int j = 0; j < 4; ++j) acc[i][j] = make_float4(0.f, 0.f, 0.f, 0.f);

    ldg_tile(0);
    sts_tile(0);
    __syncthreads();
    ldg_tile(1);

    for (int kt = 0; kt < 16; ++kt){
        const int buf = kt & 1;
        const float* As = sm + buf * SSZ;
        const float* Bs = As + 128 * STR;
#pragma unroll
        for (int kp = 0; kp < 2; ++kp){
            float4 alo[4], ahi[4], bf[4];
#pragma unroll
            for (int mi = 0; mi < 4; ++mi){
                const int br = wm * 64 + mi * 16 + r;
                alo[mi] = *(const float4*)&As[br * STR + c * 8 + kp * 4];
                ahi[mi] = *(const float4*)&As[(br + 8) * STR + c * 8 + kp * 4];
            }
#pragma unroll
            for (int ni = 0; ni < 4; ++ni){
                const int bn = wn * 32 + ni * 8 + r;
                bf[ni] = *(const float4*)&Bs[bn * STR + c * 8 + kp * 4];
            }
#pragma unroll
            for (int mi = 0; mi < 4; ++mi)
#pragma unroll
                for (int ni = 0; ni < 4; ++ni){
                    mma8(acc[mi][ni],
                         __float_as_uint(alo[mi].x), __float_as_uint(ahi[mi].x),
                         __float_as_uint(alo[mi].y), __float_as_uint(ahi[mi].y),
                         __float_as_uint(bf[ni].x),  __float_as_uint(bf[ni].y));
                    mma8(acc[mi][ni],
                         __float_as_uint(alo[mi].z), __float_as_uint(ahi[mi].z),
                         __float_as_uint(alo[mi].w), __float_as_uint(ahi[mi].w),
                         __float_as_uint(bf[ni].z),  __float_as_uint(bf[ni].w));
                }
        }
        __syncthreads();
        if (kt < 15){
            sts_tile(buf ^ 1);
            __syncthreads();
            if (kt < 14) ldg_tile(kt + 2);
        }
    }

    if (MODE == 0){
#pragma unroll
        for (int mi = 0; mi < 4; ++mi){
            const int row = m0 + wm * 64 + mi * 16 + r;
#pragma unroll
            for (int ni = 0; ni < 4; ++ni){
                const int col = n0 + wn * 32 + ni * 8 + 2 * c;
                const float b0 = __ldg(bias + col), b1 = __ldg(bias + col + 1);
                float* o0 = OUT + (size_t)row * CC + col;
                float2 v0 = {acc[mi][ni].x + b0, acc[mi][ni].y + b1};
                float2 v1 = {acc[mi][ni].z + b0, acc[mi][ni].w + b1};
                *(float2*)o0 = v0;
                *(float2*)(o0 + (size_t)8 * CC) = v1;
            }
        }
    } else {
        const int b = (m0 >= NN) ? 1 : 0;
        const int tbase = m0 - b * NN;
#pragma unroll
        for (int mi = 0; mi < 4; ++mi){
            const int ltok = wm * 64 + mi * 16 + r;
            float* ob = OUT + (size_t)b * CN + tbase + ltok;
#pragma unroll
            for (int ni = 0; ni < 4; ++ni){
                const int col = n0 + wn * 32 + ni * 8 + 2 * c;
                const float b0 = __ldg(bias + col), b1 = __ldg(bias + col + 1);
                ob[(size_t)col * NN]           = acc[mi][ni].x + b0;
                ob[(size_t)(col + 1) * NN]     = acc[mi][ni].y + b1;
                ob[(size_t)col * NN + 8]       = acc[mi][ni].z + b0;
                ob[(size_t)(col + 1) * NN + 8] = acc[mi][ni].w + b1;
            }
        }
    }
}

// ---------------------------------------------------------------------------
// Tensor-core flash attention, round 9: 32-key tiles, 53.5KB smem -> 4 blk/SM
// ---------------------------------------------------------------------------
__global__ __launch_bounds__(128, 4) void attn_mma()
{
    extern __shared__ __align__(16) float sm[];
    float* Kt = sm;                    // [2][32][KSTR]
    float* Vt = sm + OFF_V;            // [2][32][VSTR]
    float* Ps = sm + OFF_PS;           // [64][KSTR] (Q stage, P, O^T stride 65)
    float* al_s = sm + OFF_AL;         // [64] alpha / l_inv

    const int tid  = threadIdx.x;
    const int lane = tid & 31, wid = tid >> 5;
    const int g = lane >> 2, c = lane & 3;

    const int bnt = blockIdx.y, qt = blockIdx.x;
    const int b = bnt >> 7, n = (bnt >> 4) & 7, t = bnt & 15;
    const size_t base = (size_t)((b * TT + t) * PP) * CC;
    const int col0 = n * 64;
    const float* Qg = g_q + base + (size_t)qt * 64 * CC + col0;
    const float* Kg = g_k + base + col0;
    const float* Vg = g_v + base + col0;

    const uint32_t sb = smem_u32(sm);

    // one 32-key tile: 32 rows x 16 float4 chunks for K and V
    auto load_kv = [&](int kb, int buf){
#pragma unroll
        for (int it = 0; it < 4; ++it){
            const int f = tid + it * 128;
            const int row = f >> 4, ch = (f & 15) * 4;
            const uint32_t kd = sb + (uint32_t)(buf * 32 * KSTR + row * KSTR + ch) * 4u;
            const uint32_t vd = sb + (uint32_t)(OFF_V + buf * 32 * VSTR + row * VSTR + ch) * 4u;
            const float* ks = Kg + (size_t)(kb * 32 + row) * CC + ch;
            const float* vs = Vg + (size_t)(kb * 32 + row) * CC + ch;
            asm volatile("cp.async.cg.shared.global [%0], [%1], 16;" :: "r"(kd), "l"(ks));
            asm volatile("cp.async.cg.shared.global [%0], [%1], 16;" :: "r"(vd), "l"(vs));
        }
        asm volatile("cp.async.commit_group;");
    };

    load_kv(0, 0);

    // stage Q tile (64x64) into Ps
#pragma unroll
    for (int it = 0; it < 8; ++it){
        const int f = tid + it * 128;
        const int row = f >> 4, c4 = (f & 15) << 2;
        *(float4*)&Ps[row * KSTR + c4] = *(const float4*)(Qg + (size_t)row * CC + c4);
    }
    __syncthreads();

    const int mrow = wid * 16 + g;
    uint32_t qf[8][4];
#pragma unroll
    for (int kk = 0; kk < 8; ++kk){
        qf[kk][0] = __float_as_uint(Ps[ mrow      * KSTR + kk * 8 + c    ]);
        qf[kk][1] = __float_as_uint(Ps[(mrow + 8) * KSTR + kk * 8 + c    ]);
        qf[kk][2] = __float_as_uint(Ps[ mrow      * KSTR + kk * 8 + c + 4]);
        qf[kk][3] = __float_as_uint(Ps[(mrow + 8) * KSTR + kk * 8 + c + 4]);
    }

    float m_i[2] = {-1e30f, -1e30f}, l_i[2] = {0.f, 0.f};
    float4 o[8];
#pragma unroll
    for (int i = 0; i < 8; ++i) o[i] = make_float4(0.f, 0.f, 0.f, 0.f);
    const float scale = 0.125f;

    for (int kb = 0; kb < 18; ++kb){
        asm volatile("cp.async.wait_group 0;" ::: "memory");
        __syncthreads();   // tile kb visible; tile kb-1 fully consumed by all warps
        if (kb < 17) load_kv(kb + 1, (kb + 1) & 1);

        const float* Kb = Kt + (kb & 1) * 32 * KSTR;
        const float* Vb = Vt + (kb & 1) * 32 * VSTR;

        // S = Q K^T  (64q x 32k; warp: 16q x 32k)
        float4 s[4];
#pragma unroll
        for (int i = 0; i < 4; ++i) s[i] = make_float4(0.f, 0.f, 0.f, 0.f);
#pragma unroll
        for (int kk = 0; kk < 8; ++kk){
#pragma unroll
            for (int nf = 0; nf < 4; ++nf){
                const float* kr = &Kb[(nf * 8 + g) * KSTR + kk * 8 + c];
                mma8(s[nf], qf[kk][0], qf[kk][1], qf[kk][2], qf[kk][3],
                     __float_as_uint(kr[0]), __float_as_uint(kr[4]));
            }
        }

        // online softmax (rows mrow and mrow+8)
        float mx0 = -1e30f, mx1 = -1e30f;
#pragma unroll
        for (int nf = 0; nf < 4; ++nf){
            mx0 = fmaxf(mx0, fmaxf(s[nf].x, s[nf].y));
            mx1 = fmaxf(mx1, fmaxf(s[nf].z, s[nf].w));
        }
#pragma unroll
        for (int off = 1; off < 4; off <<= 1){
            mx0 = fmaxf(mx0, __shfl_xor_sync(0xffffffffu, mx0, off));
            mx1 = fmaxf(mx1, __shfl_xor_sync(0xffffffffu, mx1, off));
        }
        const float mn0 = fmaxf(m_i[0], mx0);
        const float mn1 = fmaxf(m_i[1], mx1);
        const float al0 = __expf((m_i[0] - mn0) * scale);
        const float al1 = __expf((m_i[1] - mn1) * scale);
        m_i[0] = mn0; m_i[1] = mn1;

        float rs0 = 0.f, rs1 = 0.f;
#pragma unroll
        for (int nf = 0; nf < 4; ++nf){
            float px = to_tf32(__expf((s[nf].x - mn0) * scale));
            float py = to_tf32(__expf((s[nf].y - mn0) * scale));
            float pz = to_tf32(__expf((s[nf].z - mn1) * scale));
            float pw = to_tf32(__expf((s[nf].w - mn1) * scale));
            rs0 += px + py; rs1 += pz + pw;
            *(float2*)&Ps[ mrow      * KSTR + nf * 8 + 2 * c] = make_float2(px, py);
            *(float2*)&Ps[(mrow + 8) * KSTR + nf * 8 + 2 * c] = make_float2(pz, pw);
        }
#pragma unroll
        for (int off = 1; off < 4; off <<= 1){
            rs0 += __shfl_xor_sync(0xffffffffu, rs0, off);
            rs1 += __shfl_xor_sync(0xffffffffu, rs1, off);
        }
        l_i[0] = l_i[0] * al0 + rs0;
        l_i[1] = l_i[1] * al1 + rs1;
        if (c == 0){ al_s[mrow] = al0; al_s[mrow + 8] = al1; }
        __syncthreads();   // P + alpha visible to all warps

        // scale O^T columns by alpha[p]
#pragma unroll
        for (int nf = 0; nf < 8; ++nf){
            const float a0 = al_s[nf * 8 + 2 * c];
            const float a1 = al_s[nf * 8 + 2 * c + 1];
            o[nf].x *= a0; o[nf].z *= a0;
            o[nf].y *= a1; o[nf].w *= a1;
        }

        // O^T += V^T P^T  (a = V^T 16d-slice over 32k, b = P^T 64q over 32k)
#pragma unroll
        for (int kk = 0; kk < 4; ++kk){
            const uint32_t va0 = __float_as_uint(to_tf32(Vb[(kk * 8 + c    ) * VSTR + mrow    ]));
            const uint32_t va1 = __float_as_uint(to_tf32(Vb[(kk * 8 + c    ) * VSTR + mrow + 8]));
            const uint32_t va2 = __float_as_uint(to_tf32(Vb[(kk * 8 + c + 4) * VSTR + mrow    ]));
            const uint32_t va3 = __float_as_uint(to_tf32(Vb[(kk * 8 + c + 4) * VSTR + mrow + 8]));
#pragma unroll
            for (int nf = 0; nf < 8; ++nf){
                mma8(o[nf], va0, va1, va2, va3,
                     __float_as_uint(Ps[(nf * 8 + g) * KSTR + kk * 8 + c    ]),
                     __float_as_uint(Ps[(nf * 8 + g) * KSTR + kk * 8 + c + 4]));
            }
        }
    }

    // epilogue: l_inv broadcast, O^T -> SMEM (stride 65), transpose-read, store
    __syncthreads();
    if (c == 0){ al_s[mrow] = 1.f / l_i[0]; al_s[mrow + 8] = 1.f / l_i[1]; }
#pragma unroll
    for (int nf = 0; nf < 8; ++nf){
        Ps[ mrow      * 65 + nf * 8 + 2 * c    ] = o[nf].x;
        Ps[ mrow      * 65 + nf * 8 + 2 * c + 1] = o[nf].y;
        Ps[(mrow + 8) * 65 + nf * 8 + 2 * c    ] = o[nf].z;
        Ps[(mrow + 8) * 65 + nf * 8 + 2 * c + 1] = o[nf].w;
    }
    __syncthreads();
#pragma unroll
    for (int it = 0; it < 8; ++it){
        const int f = tid + it * 128;
        const int p = f >> 4, c4 = (f & 15) << 2;
        const float li = al_s[p];
        float4 v;
        v.x = to_tf32(Ps[(c4 + 0) * 65 + p] * li);
        v.y = to_tf32(Ps[(c4 + 1) * 65 + p] * li);
        v.z = to_tf32(Ps[(c4 + 2) * 65 + p] * li);
        v.w = to_tf32(Ps[(c4 + 3) * 65 + p] * li);
        *(float4*)(g_attn + base + (size_t)(qt * 64 + p) * CC + col0 + c4) = v;
    }
}

// ---------------------------------------------------------------------------
extern "C" void kernel_launch(void* const* d_in, const int* in_sizes, int n_in,
                              void* d_out, int out_size)
{
    const float* x   = (const float*)d_in[0];
    const float* wq  = (const float*)d_in[1];
    const float* bq  = (const float*)d_in[2];
    const float* wk  = (const float*)d_in[3];
    const float* bk  = (const float*)d_in[4];
    const float* wv  = (const float*)d_in[5];
    const float* bv  = (const float*)d_in[6];
    const float* wo  = (const float*)d_in[7];
    const float* bo  = (const float*)d_in[8];
    const float* pos = (const float*)d_in[9];
    (void)in_sizes; (void)n_in; (void)out_size;

    const int gemm_smem = 2 * SSZ * sizeof(float);
    cudaFuncSetAttribute(gemm_mma<0>, cudaFuncAttributeMaxDynamicSharedMemorySize, gemm_smem);
    cudaFuncSetAttribute(gemm_mma<1>, cudaFuncAttributeMaxDynamicSharedMemorySize, gemm_smem);
    cudaFuncSetAttribute(attn_mma, cudaFuncAttributeMaxDynamicSharedMemorySize, ATT_SMEM);

    prep_w<<<1024, 256>>>(wq, wk, wv, wo);
    transpose_pos<<<dim3(288, 16, 2), 256>>>(x, pos);

    gemm_mma<0><<<dim3(144, 4, 3), 256, gemm_smem>>>(bq, bk, bv, nullptr);

    attn_mma<<<dim3(9, 256), 128, ATT_SMEM>>>();

    gemm_mma<1><<<dim3(144, 4), 256, gemm_smem>>>(bo, nullptr, nullptr, (float*)d_out);
}

// round 11
// speedup vs baseline: 1.0982x; 1.0982x over previous
#include <cuda_runtime.h>
#include <cstdint>

#define CC    512
#define TT    16
#define PP    576
#define NN    9216
#define CN    4718592
#define NHEAD 8
#define TOTAL 9437184

#define STR   36                   // GEMM: padded floats per SMEM row
#define SSZ   (2*128*STR)          // GEMM: floats per stage

// attention smem layout (floats) — 32-key tiles, double-buffered
#define KSTR  68
#define VSTR  72
#define OFF_V   (2*32*KSTR)              // 4352
#define OFF_PS  (OFF_V + 2*32*VSTR)      // 8960
#define OFF_AL  (OFF_PS + 64*KSTR)       // 13312
#define ATT_FLOATS (OFF_AL + 64)         // 13376
#define ATT_SMEM (ATT_FLOATS*4)          // 53504 B -> 4 blocks/SM

__device__ float g_xt[TOTAL];      // [tok][c]  (x + pos, tf32-rounded)
__device__ float g_q[TOTAL];       // token-major [b][t][p][512]
__device__ float g_k[TOTAL];
__device__ float g_v[TOTAL];
__device__ float g_attn[TOTAL];    // [tok][c]  (tf32-rounded)
__device__ float g_wr[4*CC*CC];    // tf32-rounded wq,wk,wv,wo

__device__ __forceinline__ float to_tf32(float x){
    float r; asm("cvt.rna.tf32.f32 %0, %1;" : "=f"(r) : "f"(x)); return r;
}
__device__ __forceinline__ uint32_t smem_u32(const void* p){
    uint32_t a;
    asm("{ .reg .u64 t; cvta.to.shared.u64 t, %1; cvt.u32.u64 %0, t; }"
        : "=r"(a) : "l"(p));
    return a;
}

__device__ __forceinline__ void mma8(float4& d,
    uint32_t a0, uint32_t a1, uint32_t a2, uint32_t a3,
    uint32_t b0, uint32_t b1)
{
    asm volatile(
        "mma.sync.aligned.m16n8k8.row.col.f32.tf32.tf32.f32 "
        "{%0,%1,%2,%3}, {%4,%5,%6,%7}, {%8,%9}, {%0,%1,%2,%3};"
        : "+f"(d.x), "+f"(d.y), "+f"(d.z), "+f"(d.w)
        : "r"(a0), "r"(a1), "r"(a2), "r"(a3), "r"(b0), "r"(b1));
}

// ---------------------------------------------------------------------------
// prep: round weights to tf32 into g_wr
// ---------------------------------------------------------------------------
__global__ void prep_w(const float* __restrict__ wq, const float* __restrict__ wk,
                       const float* __restrict__ wv, const float* __restrict__ wo){
    int i = blockIdx.x * 256 + threadIdx.x;
    g_wr[i]          = to_tf32(wq[i]);
    g_wr[262144 + i] = to_tf32(wk[i]);
    g_wr[524288 + i] = to_tf32(wv[i]);
    g_wr[786432 + i] = to_tf32(wo[i]);
}

// ---------------------------------------------------------------------------
// transpose x[b][c][n] + pos[c][t] -> g_xt[b*9216+n][c]  (tf32-rounded)
// ---------------------------------------------------------------------------
__global__ __launch_bounds__(256) void transpose_pos(
    const float* __restrict__ x, const float* __restrict__ pos){
    __shared__ float tile[32][33];
    const int n0 = blockIdx.x * 32, c0 = blockIdx.y * 32, b = blockIdx.z;
    const int tx = threadIdx.x & 31, ty = threadIdx.x >> 5;
    const int t = n0 / PP;
#pragma unroll
    for (int i = 0; i < 4; ++i){
        const int c = c0 + ty + i * 8;
        tile[ty + i * 8][tx] =
            to_tf32(x[((size_t)b * CC + c) * NN + n0 + tx] + pos[c * TT + t]);
    }
    __syncthreads();
#pragma unroll
    for (int i = 0; i < 4; ++i){
        const int n = n0 + ty + i * 8;
        g_xt[((size_t)b * NN + n) * CC + c0 + tx] = tile[tx][ty + i * 8];
    }
}

// ---------------------------------------------------------------------------
// mma.sync tf32 GEMM — round 10: single __syncthreads per k-step.
// Order per kt: STS(tile kt+1, staged in regs) -> LDG(tile kt+2) -> MMA(kt)
//  -> sync. WAR on buf^1 is protected by the previous iteration's barrier.
// ---------------------------------------------------------------------------
template<int MODE>
__global__ __launch_bounds__(256) void gemm_mma(
    const float* __restrict__ bi0, const float* __restrict__ bi1,
    const float* __restrict__ bi2, float* __restrict__ o_out)
{
    extern __shared__ float sm[];

    const int tid = threadIdx.x;
    const int m0 = blockIdx.x * 128;
    const int n0 = blockIdx.y * 128;

    const float* A;
    const float* Bw;
    const float* bias;
    float* OUT;
    if (MODE == 0){
        const int pr = blockIdx.z;
        A    = g_xt + (size_t)m0 * CC;
        Bw   = g_wr + (size_t)pr * 262144 + (size_t)n0 * CC;
        bias = (pr == 0) ? bi0 : (pr == 1) ? bi1 : bi2;
        OUT  = (pr == 0) ? g_q : (pr == 1) ? g_k : g_v;
    } else {
        A    = g_attn + (size_t)m0 * CC;
        Bw   = g_wr + 786432 + (size_t)n0 * CC;
        bias = bi0;
        OUT  = o_out;
    }

    const int row_l = tid >> 3;
    const int jl    = tid & 7;
    const int wid = tid >> 5, lane = tid & 31;
    const int wm = wid >> 2, wn = wid & 3;
    const int r = lane >> 2, c = lane & 3;

    float4 pa[4], pb[4];

    auto ldg_tile = [&](int kt){
#pragma unroll
        for (int p = 0; p < 4; ++p){
            pa[p] = *(const float4*)(A  + (size_t)(row_l + p * 32) * CC + kt * 32 + jl * 4);
            pb[p] = *(const float4*)(Bw + (size_t)(row_l + p * 32) * CC + kt * 32 + jl * 4);
        }
    };
    auto sts_tile = [&](int buf){
        float* As = sm + buf * SSZ;
        float* Bs = As + 128 * STR;
#pragma unroll
        for (int p = 0; p < 4; ++p){
            const int ro = (row_l + p * 32) * STR;
            As[ro + 0 * 8 + jl] = pa[p].x;
            As[ro + 1 * 8 + jl] = pa[p].y;
            As[ro + 2 * 8 + jl] = pa[p].z;
            As[ro + 3 * 8 + jl] = pa[p].w;
            Bs[ro + 0 * 8 + jl] = pb[p].x;
            Bs[ro + 1 * 8 + jl] = pb[p].y;
            Bs[ro + 2 * 8 + jl] = pb[p].z;
            Bs[ro + 3 * 8 + jl] = pb[p].w;
        }
    };

    float4 acc[4][4];
#pragma unroll
    for (int i = 0; i < 4; ++i)
#pragma unroll
        for (int j = 0; j < 4; ++j) acc[i][j] = make_float4(0.f, 0.f, 0.f, 0.f);

    ldg_tile(0);
    sts_tile(0);
    __syncthreads();           // stage 0 visible to all warps
    ldg_tile(1);               // regs hold tile 1

    for (int kt = 0; kt < 16; ++kt){
        const int buf = kt & 1;
        // store tile kt+1 into the buffer consumed at kt-1 (barrier-protected)
        if (kt < 15) sts_tile(buf ^ 1);
        // prefetch tile kt+2 into regs (overwrites pa/pb after STS consumed them)
        if (kt < 14) ldg_tile(kt + 2);

        const float* As = sm + buf * SSZ;
        const float* Bs = As + 128 * STR;
#pragma unroll
        for (int kp = 0; kp < 2; ++kp){
            float4 alo[4], ahi[4], bf[4];
#pragma unroll
            for (int mi = 0; mi < 4; ++mi){
                const int br = wm * 64 + mi * 16 + r;
                alo[mi] = *(const float4*)&As[br * STR + c * 8 + kp * 4];
                ahi[mi] = *(const float4*)&As[(br + 8) * STR + c * 8 + kp * 4];
            }
#pragma unroll
            for (int ni = 0; ni < 4; ++ni){
                const int bn = wn * 32 + ni * 8 + r;
                bf[ni] = *(const float4*)&Bs[bn * STR + c * 8 + kp * 4];
            }
#pragma unroll
            for (int mi = 0; mi < 4; ++mi)
#pragma unroll
                for (int ni = 0; ni < 4; ++ni){
                    mma8(acc[mi][ni],
                         __float_as_uint(alo[mi].x), __float_as_uint(ahi[mi].x),
                         __float_as_uint(alo[mi].y), __float_as_uint(ahi[mi].y),
                         __float_as_uint(bf[ni].x),  __float_as_uint(bf[ni].y));
                    mma8(acc[mi][ni],
                         __float_as_uint(alo[mi].z), __float_as_uint(ahi[mi].z),
                         __float_as_uint(alo[mi].w), __float_as_uint(ahi[mi].w),
                         __float_as_uint(bf[ni].z),  __float_as_uint(bf[ni].w));
                }
        }
        __syncthreads();       // tile kt consumed by all; tile kt+1 visible
    }

    if (MODE == 0){
#pragma unroll
        for (int mi = 0; mi < 4; ++mi){
            const int row = m0 + wm * 64 + mi * 16 + r;
#pragma unroll
            for (int ni = 0; ni < 4; ++ni){
                const int col = n0 + wn * 32 + ni * 8 + 2 * c;
                const float b0 = __ldg(bias + col), b1 = __ldg(bias + col + 1);
                float* o0 = OUT + (size_t)row * CC + col;
                float2 v0 = {acc[mi][ni].x + b0, acc[mi][ni].y + b1};
                float2 v1 = {acc[mi][ni].z + b0, acc[mi][ni].w + b1};
                *(float2*)o0 = v0;
                *(float2*)(o0 + (size_t)8 * CC) = v1;
            }
        }
    } else {
        const int b = (m0 >= NN) ? 1 : 0;
        const int tbase = m0 - b * NN;
#pragma unroll
        for (int mi = 0; mi < 4; ++mi){
            const int ltok = wm * 64 + mi * 16 + r;
            float* ob = OUT + (size_t)b * CN + tbase + ltok;
#pragma unroll
            for (int ni = 0; ni < 4; ++ni){
                const int col = n0 + wn * 32 + ni * 8 + 2 * c;
                const float b0 = __ldg(bias + col), b1 = __ldg(bias + col + 1);
                ob[(size_t)col * NN]           = acc[mi][ni].x + b0;
                ob[(size_t)(col + 1) * NN]     = acc[mi][ni].y + b1;
                ob[(size_t)col * NN + 8]       = acc[mi][ni].z + b0;
                ob[(size_t)(col + 1) * NN + 8] = acc[mi][ni].w + b1;
            }
        }
    }
}

// ---------------------------------------------------------------------------
// Tensor-core flash attention (round 9, unchanged): 32-key tiles, 4 blk/SM
// ---------------------------------------------------------------------------
__global__ __launch_bounds__(128, 4) void attn_mma()
{
    extern __shared__ __align__(16) float sm[];
    float* Kt = sm;                    // [2][32][KSTR]
    float* Vt = sm + OFF_V;            // [2][32][VSTR]
    float* Ps = sm + OFF_PS;           // [64][KSTR] (Q stage, P, O^T stride 65)
    float* al_s = sm + OFF_AL;         // [64] alpha / l_inv

    const int tid  = threadIdx.x;
    const int lane = tid & 31, wid = tid >> 5;
    const int g = lane >> 2, c = lane & 3;

    const int bnt = blockIdx.y, qt = blockIdx.x;
    const int b = bnt >> 7, n = (bnt >> 4) & 7, t = bnt & 15;
    const size_t base = (size_t)((b * TT + t) * PP) * CC;
    const int col0 = n * 64;
    const float* Qg = g_q + base + (size_t)qt * 64 * CC + col0;
    const float* Kg = g_k + base + col0;
    const float* Vg = g_v + base + col0;

    const uint32_t sb = smem_u32(sm);

    auto load_kv = [&](int kb, int buf){
#pragma unroll
        for (int it = 0; it < 4; ++it){
            const int f = tid + it * 128;
            const int row = f >> 4, ch = (f & 15) * 4;
            const uint32_t kd = sb + (uint32_t)(buf * 32 * KSTR + row * KSTR + ch) * 4u;
            const uint32_t vd = sb + (uint32_t)(OFF_V + buf * 32 * VSTR + row * VSTR + ch) * 4u;
            const float* ks = Kg + (size_t)(kb * 32 + row) * CC + ch;
            const float* vs = Vg + (size_t)(kb * 32 + row) * CC + ch;
            asm volatile("cp.async.cg.shared.global [%0], [%1], 16;" :: "r"(kd), "l"(ks));
            asm volatile("cp.async.cg.shared.global [%0], [%1], 16;" :: "r"(vd), "l"(vs));
        }
        asm volatile("cp.async.commit_group;");
    };

    load_kv(0, 0);

    // stage Q tile (64x64) into Ps
#pragma unroll
    for (int it = 0; it < 8; ++it){
        const int f = tid + it * 128;
        const int row = f >> 4, c4 = (f & 15) << 2;
        *(float4*)&Ps[row * KSTR + c4] = *(const float4*)(Qg + (size_t)row * CC + c4);
    }
    __syncthreads();

    const int mrow = wid * 16 + g;
    uint32_t qf[8][4];
#pragma unroll
    for (int kk = 0; kk < 8; ++kk){
        qf[kk][0] = __float_as_uint(Ps[ mrow      * KSTR + kk * 8 + c    ]);
        qf[kk][1] = __float_as_uint(Ps[(mrow + 8) * KSTR + kk * 8 + c    ]);
        qf[kk][2] = __float_as_uint(Ps[ mrow      * KSTR + kk * 8 + c + 4]);
        qf[kk][3] = __float_as_uint(Ps[(mrow + 8) * KSTR + kk * 8 + c + 4]);
    }

    float m_i[2] = {-1e30f, -1e30f}, l_i[2] = {0.f, 0.f};
    float4 o[8];
#pragma unroll
    for (int i = 0; i < 8; ++i) o[i] = make_float4(0.f, 0.f, 0.f, 0.f);
    const float scale = 0.125f;

    for (int kb = 0; kb < 18; ++kb){
        asm volatile("cp.async.wait_group 0;" ::: "memory");
        __syncthreads();
        if (kb < 17) load_kv(kb + 1, (kb + 1) & 1);

        const float* Kb = Kt + (kb & 1) * 32 * KSTR;
        const float* Vb = Vt + (kb & 1) * 32 * VSTR;

        float4 s[4];
#pragma unroll
        for (int i = 0; i < 4; ++i) s[i] = make_float4(0.f, 0.f, 0.f, 0.f);
#pragma unroll
        for (int kk = 0; kk < 8; ++kk){
#pragma unroll
            for (int nf = 0; nf < 4; ++nf){
                const float* kr = &Kb[(nf * 8 + g) * KSTR + kk * 8 + c];
                mma8(s[nf], qf[kk][0], qf[kk][1], qf[kk][2], qf[kk][3],
                     __float_as_uint(kr[0]), __float_as_uint(kr[4]));
            }
        }

        float mx0 = -1e30f, mx1 = -1e30f;
#pragma unroll
        for (int nf = 0; nf < 4; ++nf){
            mx0 = fmaxf(mx0, fmaxf(s[nf].x, s[nf].y));
            mx1 = fmaxf(mx1, fmaxf(s[nf].z, s[nf].w));
        }
#pragma unroll
        for (int off = 1; off < 4; off <<= 1){
            mx0 = fmaxf(mx0, __shfl_xor_sync(0xffffffffu, mx0, off));
            mx1 = fmaxf(mx1, __shfl_xor_sync(0xffffffffu, mx1, off));
        }
        const float mn0 = fmaxf(m_i[0], mx0);
        const float mn1 = fmaxf(m_i[1], mx1);
        const float al0 = __expf((m_i[0] - mn0) * scale);
        const float al1 = __expf((m_i[1] - mn1) * scale);
        m_i[0] = mn0; m_i[1] = mn1;

        float rs0 = 0.f, rs1 = 0.f;
#pragma unroll
        for (int nf = 0; nf < 4; ++nf){
            float px = to_tf32(__expf((s[nf].x - mn0) * scale));
            float py = to_tf32(__expf((s[nf].y - mn0) * scale));
            float pz = to_tf32(__expf((s[nf].z - mn1) * scale));
            float pw = to_tf32(__expf((s[nf].w - mn1) * scale));
            rs0 += px + py; rs1 += pz + pw;
            *(float2*)&Ps[ mrow      * KSTR + nf * 8 + 2 * c] = make_float2(px, py);
            *(float2*)&Ps[(mrow + 8) * KSTR + nf * 8 + 2 * c] = make_float2(pz, pw);
        }
#pragma unroll
        for (int off = 1; off < 4; off <<= 1){
            rs0 += __shfl_xor_sync(0xffffffffu, rs0, off);
            rs1 += __shfl_xor_sync(0xffffffffu, rs1, off);
        }
        l_i[0] = l_i[0] * al0 + rs0;
        l_i[1] = l_i[1] * al1 + rs1;
        if (c == 0){ al_s[mrow] = al0; al_s[mrow + 8] = al1; }
        __syncthreads();

#pragma unroll
        for (int nf = 0; nf < 8; ++nf){
            const float a0 = al_s[nf * 8 + 2 * c];
            const float a1 = al_s[nf * 8 + 2 * c + 1];
            o[nf].x *= a0; o[nf].z *= a0;
            o[nf].y *= a1; o[nf].w *= a1;
        }

#pragma unroll
        for (int kk = 0; kk < 4; ++kk){
            const uint32_t va0 = __float_as_uint(to_tf32(Vb[(kk * 8 + c    ) * VSTR + mrow    ]));
            const uint32_t va1 = __float_as_uint(to_tf32(Vb[(kk * 8 + c    ) * VSTR + mrow + 8]));
            const uint32_t va2 = __float_as_uint(to_tf32(Vb[(kk * 8 + c + 4) * VSTR + mrow    ]));
            const uint32_t va3 = __float_as_uint(to_tf32(Vb[(kk * 8 + c + 4) * VSTR + mrow + 8]));
#pragma unroll
            for (int nf = 0; nf < 8; ++nf){
                mma8(o[nf], va0, va1, va2, va3,
                     __float_as_uint(Ps[(nf * 8 + g) * KSTR + kk * 8 + c    ]),
                     __float_as_uint(Ps[(nf * 8 + g) * KSTR + kk * 8 + c + 4]));
            }
        }
    }

    __syncthreads();
    if (c == 0){ al_s[mrow] = 1.f / l_i[0]; al_s[mrow + 8] = 1.f / l_i[1]; }
#pragma unroll
    for (int nf = 0; nf < 8; ++nf){
        Ps[ mrow      * 65 + nf * 8 + 2 * c    ] = o[nf].x;
        Ps[ mrow      * 65 + nf * 8 + 2 * c + 1] = o[nf].y;
        Ps[(mrow + 8) * 65 + nf * 8 + 2 * c    ] = o[nf].z;
        Ps[(mrow + 8) * 65 + nf * 8 + 2 * c + 1] = o[nf].w;
    }
    __syncthreads();
#pragma unroll
    for (int it = 0; it < 8; ++it){
        const int f = tid + it * 128;
        const int p = f >> 4, c4 = (f & 15) << 2;
        const float li = al_s[p];
        float4 v;
        v.x = to_tf32(Ps[(c4 + 0) * 65 + p] * li);
        v.y = to_tf32(Ps[(c4 + 1) * 65 + p] * li);
        v.z = to_tf32(Ps[(c4 + 2) * 65 + p] * li);
        v.w = to_tf32(Ps[(c4 + 3) * 65 + p] * li);
        *(float4*)(g_attn + base + (size_t)(qt * 64 + p) * CC + col0 + c4) = v;
    }
}

// ---------------------------------------------------------------------------
extern "C" void kernel_launch(void* const* d_in, const int* in_sizes, int n_in,
                              void* d_out, int out_size)
{
    const float* x   = (const float*)d_in[0];
    const float* wq  = (const float*)d_in[1];
    const float* bq  = (const float*)d_in[2];
    const float* wk  = (const float*)d_in[3];
    const float* bk  = (const float*)d_in[4];
    const float* wv  = (const float*)d_in[5];
    const float* bv  = (const float*)d_in[6];
    const float* wo  = (const float*)d_in[7];
    const float* bo  = (const float*)d_in[8];
    const float* pos = (const float*)d_in[9];
    (void)in_sizes; (void)n_in; (void)out_size;

    const int gemm_smem = 2 * SSZ * sizeof(float);
    cudaFuncSetAttribute(gemm_mma<0>, cudaFuncAttributeMaxDynamicSharedMemorySize, gemm_smem);
    cudaFuncSetAttribute(gemm_mma<1>, cudaFuncAttributeMaxDynamicSharedMemorySize, gemm_smem);
    cudaFuncSetAttribute(attn_mma, cudaFuncAttributeMaxDynamicSharedMemorySize, ATT_SMEM);

    prep_w<<<1024, 256>>>(wq, wk, wv, wo);
    transpose_pos<<<dim3(288, 16, 2), 256>>>(x, pos);

    gemm_mma<0><<<dim3(144, 4, 3), 256, gemm_smem>>>(bq, bk, bv, nullptr);

    attn_mma<<<dim3(9, 256), 128, ATT_SMEM>>>();

    gemm_mma<1><<<dim3(144, 4), 256, gemm_smem>>>(bo, nullptr, nullptr, (float*)d_out);
}